// round 7
// baseline (speedup 1.0000x reference)
#include <cuda_runtime.h>
#include <cuda_fp16.h>
#include <cuda_bf16.h>

#define N_NODES_MAX 100352
#define N_EDGES_MAX 1605632
#define FEATS 128
#define NGRAPH 128
#define NCLASS 64
#define SCAN_TILE 4096

// ---------------- scratch (device globals) ----------------------------------
__device__ int    g_deg_out[2][N_NODES_MAX];
__device__ int    g_deg_in[2][N_NODES_MAX];
__device__ int    g_row_ptr[2][N_NODES_MAX];
__device__ int    g_cursor[2][N_NODES_MAX];
__device__ int    g_csr_src[2][N_EDGES_MAX];
__device__ __half g_h[2][(size_t)N_NODES_MAX * FEATS];
__device__ __half g_WT[FEATS * FEATS];           // W^T in fp16: [n][k]
__device__ float  g_hg[2 * NGRAPH * FEATS];
__device__ int    g_cnt[2 * NGRAPH];
__device__ int    g_part[2 * 64];
__device__ int    g_part_scan[2 * 64];

// ---------------- W transpose + fp16 convert --------------------------------
__global__ void prep_wt_kernel(const float* __restrict__ W) {
    int t = blockIdx.x * blockDim.x + threadIdx.x;   // 16384
    int k = t >> 7, n = t & 127;
    g_WT[n * 128 + k] = __float2half_rn(W[k * 128 + n]);
}

// ---------------- degrees, both branches ------------------------------------
__global__ void degree2_kernel(const int* __restrict__ s1, const int* __restrict__ d1, int E1,
                               const int* __restrict__ s2, const int* __restrict__ d2, int E2) {
    int e = blockIdx.x * blockDim.x + threadIdx.x;
    if (e < E1) {
        atomicAdd(&g_deg_out[0][s1[e]], 1);
        atomicAdd(&g_deg_in[0][d1[e]], 1);
    } else if (e < E1 + E2) {
        int i = e - E1;
        atomicAdd(&g_deg_out[1][s2[i]], 1);
        atomicAdd(&g_deg_in[1][d2[i]], 1);
    }
}

// ---------------- scan phase 1: per-tile sums --------------------------------
__global__ void reduce_kernel(int nnodes) {
    int br = blockIdx.y, blk = blockIdx.x;
    int i = blk * SCAN_TILE + threadIdx.x * 4;
    int lane = threadIdx.x & 31, w = threadIdx.x >> 5;
    int s = 0;
    if (i + 3 < nnodes) {
        int4 v = *(const int4*)&g_deg_in[br][i];
        s = v.x + v.y + v.z + v.w;
    } else {
        for (int k = 0; k < 4; k++) if (i + k < nnodes) s += g_deg_in[br][i + k];
    }
#pragma unroll
    for (int o = 16; o; o >>= 1) s += __shfl_xor_sync(0xffffffffu, s, o);
    __shared__ int ws[32];
    if (lane == 0) ws[w] = s;
    __syncthreads();
    if (threadIdx.x < 32) {
        int t = ws[threadIdx.x];
#pragma unroll
        for (int o = 16; o; o >>= 1) t += __shfl_xor_sync(0xffffffffu, t, o);
        if (threadIdx.x == 0) g_part[br * 64 + blk] = t;
    }
}

// ---------------- scan phase 2: scan tile sums (1 block, warp per branch) ----
__global__ void scan_part_kernel(int nblk) {
    int br = threadIdx.x >> 5, lane = threadIdx.x & 31;
    if (br >= 2) return;
    int v = (lane < nblk) ? g_part[br * 64 + lane] : 0;
    int x = v;
#pragma unroll
    for (int o = 1; o < 32; o <<= 1) {
        int y = __shfl_up_sync(0xffffffffu, x, o);
        if (lane >= o) x += y;
    }
    g_part_scan[br * 64 + lane] = x - v;
}

// ---------------- scan phase 3: local rescan -> row_ptr & cursor -------------
__global__ void local_scan_kernel(int nnodes) {
    int br = blockIdx.y, blk = blockIdx.x;
    int i = blk * SCAN_TILE + threadIdx.x * 4;
    int lane = threadIdx.x & 31, w = threadIdx.x >> 5;
    int4 v = make_int4(0, 0, 0, 0);
    if (i + 3 < nnodes) v = *(const int4*)&g_deg_in[br][i];
    else {
        if (i     < nnodes) v.x = g_deg_in[br][i];
        if (i + 1 < nnodes) v.y = g_deg_in[br][i + 1];
        if (i + 2 < nnodes) v.z = g_deg_in[br][i + 2];
    }
    int s0 = v.x, s1 = s0 + v.y, s2 = s1 + v.z, s3 = s2 + v.w;
    int x = s3;
#pragma unroll
    for (int o = 1; o < 32; o <<= 1) {
        int y = __shfl_up_sync(0xffffffffu, x, o);
        if (lane >= o) x += y;
    }
    __shared__ int ws[32];
    if (lane == 31) ws[w] = x;
    __syncthreads();
    if (w == 0) {
        int t = ws[lane];
#pragma unroll
        for (int o = 1; o < 32; o <<= 1) {
            int y = __shfl_up_sync(0xffffffffu, t, o);
            if (lane >= o) t += y;
        }
        ws[lane] = t;
    }
    __syncthreads();
    int base = g_part_scan[br * 64 + blk] + (w ? ws[w - 1] : 0) + (x - s3);
    int4 e = make_int4(base, base + s0, base + s1, base + s2);
    if (i + 3 < nnodes) {
        *(int4*)&g_row_ptr[br][i] = e;
        *(int4*)&g_cursor[br][i]  = e;
    } else {
        if (i     < nnodes) { g_row_ptr[br][i]     = e.x; g_cursor[br][i]     = e.x; }
        if (i + 1 < nnodes) { g_row_ptr[br][i + 1] = e.y; g_cursor[br][i + 1] = e.y; }
        if (i + 2 < nnodes) { g_row_ptr[br][i + 2] = e.z; g_cursor[br][i + 2] = e.z; }
    }
}

// ---------------- CSR fill, both branches ------------------------------------
__global__ void fill2_kernel(const int* __restrict__ s1, const int* __restrict__ d1, int E1,
                             const int* __restrict__ s2, const int* __restrict__ d2, int E2) {
    int e = blockIdx.x * blockDim.x + threadIdx.x;
    if (e < E1) {
        int pos = atomicAdd(&g_cursor[0][d1[e]], 1);
        g_csr_src[0][pos] = s1[e];
    } else if (e < E1 + E2) {
        int i = e - E1;
        int pos = atomicAdd(&g_cursor[1][d2[i]], 1);
        g_csr_src[1][pos] = s2[i];
    }
}

// ---------------- fp16 MMA helper --------------------------------------------
__device__ __forceinline__ void mma_f16(float4& c,
                                        unsigned a0, unsigned a1,
                                        unsigned a2, unsigned a3,
                                        unsigned b0, unsigned b1) {
    asm volatile(
        "mma.sync.aligned.m16n8k16.row.col.f32.f16.f16.f32 "
        "{%0,%1,%2,%3}, {%4,%5,%6,%7}, {%8,%9}, {%0,%1,%2,%3};\n"
        : "+f"(c.x), "+f"(c.y), "+f"(c.z), "+f"(c.w)
        : "r"(a0), "r"(a1), "r"(a2), "r"(a3), "r"(b0), "r"(b1));
}

// ---------------- GEMM (fp16 HMMA): g_h[br] = ds * (feat @ W), fp16 out ------
#define AS 136  // half stride per smem row (272B) -> conflict-free
__global__ void __launch_bounds__(256, 2)
gemm_fp16_kernel(const float* __restrict__ feat0, const float* __restrict__ feat1,
                 int nnodes) {
    extern __shared__ __half sm[];
    __half* sA  = sm;              // [128][AS]  feat tile (fp16), row-major
    __half* sBt = sm + 128 * AS;   // [128][AS]  W^T: [n][k]

    const int br   = blockIdx.y;
    const float* feat = br ? feat1 : feat0;
    const int tid  = threadIdx.x;
    const int row0 = blockIdx.x * 128;
    const float4* F4  = (const float4*)feat;
    const uint4*  WT4 = (const uint4*)g_WT;

#pragma unroll
    for (int i = 0; i < 8; i++) {
        int idx = tid + i * 256;          // 2048 uint4 total
        int r = idx >> 4, c = idx & 15;   // row, uint4-col (8 halves)
        float4 f0 = make_float4(0.f, 0.f, 0.f, 0.f), f1 = f0;
        if (row0 + r < nnodes) {
            f0 = F4[(size_t)(row0 + r) * 32 + 2 * c];
            f1 = F4[(size_t)(row0 + r) * 32 + 2 * c + 1];
        }
        union { __half2 h[4]; uint4 u; } p;
        p.h[0] = __floats2half2_rn(f0.x, f0.y);
        p.h[1] = __floats2half2_rn(f0.z, f0.w);
        p.h[2] = __floats2half2_rn(f1.x, f1.y);
        p.h[3] = __floats2half2_rn(f1.z, f1.w);
        *(uint4*)&sA[r * AS + c * 8] = p.u;
        *(uint4*)&sBt[r * AS + c * 8] = WT4[idx];
    }
    __syncthreads();

    const int w = tid >> 5, lane = tid & 31;
    const int gid8 = lane >> 2, tig = lane & 3;
    const int r0 = w * 16;

    float4 c[16];
#pragma unroll
    for (int j = 0; j < 16; j++) c[j] = make_float4(0.f, 0.f, 0.f, 0.f);

#pragma unroll
    for (int kk = 0; kk < 8; kk++) {
        int k0 = kk * 16;
        unsigned a0 = *(const unsigned*)&sA[(r0 + gid8) * AS + k0 + 2 * tig];
        unsigned a1 = *(const unsigned*)&sA[(r0 + gid8 + 8) * AS + k0 + 2 * tig];
        unsigned a2 = *(const unsigned*)&sA[(r0 + gid8) * AS + k0 + 8 + 2 * tig];
        unsigned a3 = *(const unsigned*)&sA[(r0 + gid8 + 8) * AS + k0 + 8 + 2 * tig];
#pragma unroll
        for (int j = 0; j < 16; j++) {
            unsigned b0 = *(const unsigned*)&sBt[(j * 8 + gid8) * AS + k0 + 2 * tig];
            unsigned b1 = *(const unsigned*)&sBt[(j * 8 + gid8) * AS + k0 + 8 + 2 * tig];
            mma_f16(c[j], a0, a1, a2, a3, b0, b1);
        }
    }

    int ra = row0 + r0 + gid8;
    int rb = ra + 8;
    bool va = ra < nnodes, vb = rb < nnodes;
    float dsa = 0.f, dsb = 0.f;
    if (va) { int d = g_deg_out[br][ra]; dsa = rsqrtf((float)(d > 1 ? d : 1)); }
    if (vb) { int d = g_deg_out[br][rb]; dsb = rsqrtf((float)(d > 1 ? d : 1)); }
    unsigned* H = (unsigned*)g_h[br];
#pragma unroll
    for (int j = 0; j < 16; j++) {
        int colw = j * 4 + tig;  // half2 index within row (64 per row)
        if (va) {
            __half2 o = __floats2half2_rn(c[j].x * dsa, c[j].y * dsa);
            H[(size_t)ra * 64 + colw] = *(unsigned*)&o;
        }
        if (vb) {
            __half2 o = __floats2half2_rn(c[j].z * dsb, c[j].w * dsb);
            H[(size_t)rb * 64 + colw] = *(unsigned*)&o;
        }
    }
}

// ------- gather-aggregate + fused epilogue (HALF-WARP per node, uint4) -------
__global__ void gather2_kernel(const int* __restrict__ gid0,
                               const int* __restrict__ gid1,
                               const float* __restrict__ bvec, int nnodes) {
    int t = blockIdx.x * blockDim.x + threadIdx.x;
    int n2 = t >> 4;
    if (n2 >= 2 * nnodes) return;
    int br = (n2 >= nnodes) ? 1 : 0;
    int n = n2 - br * nnodes;
    int lane = t & 15;
    unsigned hmask = 0xFFFFu << (threadIdx.x & 16);

    int beg = g_row_ptr[br][n];
    int dg  = g_deg_in[br][n];
    int end = beg + dg;
    const uint4* H4 = (const uint4*)g_h[br];   // 16B per lane = 8 halves
    const int* csr = g_csr_src[br];

    float acc[8];
#pragma unroll
    for (int i = 0; i < 8; i++) acc[i] = 0.f;

#define ACC8(u) { float2 f_; \
    f_ = __half22float2(*(__half2*)&(u).x); acc[0] += f_.x; acc[1] += f_.y; \
    f_ = __half22float2(*(__half2*)&(u).y); acc[2] += f_.x; acc[3] += f_.y; \
    f_ = __half22float2(*(__half2*)&(u).z); acc[4] += f_.x; acc[5] += f_.y; \
    f_ = __half22float2(*(__half2*)&(u).w); acc[6] += f_.x; acc[7] += f_.y; }

    int e = beg;
    for (; e + 4 <= end; e += 4) {
        int s0 = __ldg(csr + e);
        int s1 = __ldg(csr + e + 1);
        int s2 = __ldg(csr + e + 2);
        int s3 = __ldg(csr + e + 3);
        uint4 u0 = H4[(size_t)s0 * 16 + lane];
        uint4 u1 = H4[(size_t)s1 * 16 + lane];
        uint4 u2 = H4[(size_t)s2 * 16 + lane];
        uint4 u3 = H4[(size_t)s3 * 16 + lane];
        ACC8(u0); ACC8(u1); ACC8(u2); ACC8(u3);
    }
    for (; e < end; e++) {
        int s = __ldg(csr + e);
        uint4 u = H4[(size_t)s * 16 + lane];
        ACC8(u);
    }
#undef ACC8

    float din = rsqrtf((float)(dg > 1 ? dg : 1));
    float4 b0 = __ldg((const float4*)bvec + lane * 2);
    float4 b1 = __ldg((const float4*)bvec + lane * 2 + 1);
    float v[8];
    v[0] = acc[0] * din + b0.x; v[1] = acc[1] * din + b0.y;
    v[2] = acc[2] * din + b0.z; v[3] = acc[3] * din + b0.w;
    v[4] = acc[4] * din + b1.x; v[5] = acc[5] * din + b1.y;
    v[6] = acc[6] * din + b1.z; v[7] = acc[7] * din + b1.w;

    float ss = 0.f;
#pragma unroll
    for (int i = 0; i < 8; i++) ss += v[i] * v[i];
#pragma unroll
    for (int o = 8; o; o >>= 1) ss += __shfl_xor_sync(hmask, ss, o);
    float inv = 1.f / fmaxf(sqrtf(ss), 1e-12f);

#pragma unroll
    for (int i = 0; i < 8; i++) v[i] = 1.f / (1.f + __expf(-v[i] * inv));

    const int* gid = br ? gid1 : gid0;
    int g = __ldg(gid + n);
    float4* hgp = (float4*)g_hg + (size_t)(br * NGRAPH + g) * 32 + lane * 2;
    atomicAdd(hgp,     make_float4(v[0], v[1], v[2], v[3]));
    atomicAdd(hgp + 1, make_float4(v[4], v[5], v[6], v[7]));
    if (lane == 0) atomicAdd(&g_cnt[br * NGRAPH + g], 1);
}

// ---------------- classifier + pairwise distance (block per graph) -----------
__global__ void final_kernel(const float* __restrict__ Wc,
                             const float* __restrict__ bc,
                             float* __restrict__ out) {
    int g = blockIdx.x, tid = threadIdx.x;  // 64 threads
    __shared__ float s1[128], s2[128];
    __shared__ float part[2];

    float c1 = fmaxf((float)g_cnt[g], 1.f);
    float c2 = fmaxf((float)g_cnt[NGRAPH + g], 1.f);
    for (int i = tid; i < 128; i += 64) {
        s1[i] = g_hg[g * 128 + i] / c1;
        s2[i] = g_hg[NGRAPH * 128 + g * 128 + i] / c2;
    }
    __syncthreads();

    float l1 = bc[tid], l2 = l1;
#pragma unroll 4
    for (int k = 0; k < 128; k++) {
        float w = Wc[k * NCLASS + tid];
        l1 += s1[k] * w;
        l2 += s2[k] * w;
    }
    float dd = l1 - l2 + 1e-6f;
    float sq = dd * dd;
#pragma unroll
    for (int o = 16; o; o >>= 1) sq += __shfl_xor_sync(0xffffffffu, sq, o);
    if ((tid & 31) == 0) part[tid >> 5] = sq;
    __syncthreads();
    if (tid == 0) out[g] = sqrtf(part[0] + part[1]);
}

// ---------------- launch ------------------------------------------------------
extern "C" void kernel_launch(void* const* d_in, const int* in_sizes, int n_in,
                              void* d_out, int out_size) {
    const float* feat1 = (const float*)d_in[0];
    const float* feat2 = (const float*)d_in[1];
    const int* src1 = (const int*)d_in[2];
    const int* dst1 = (const int*)d_in[3];
    const int* gid1 = (const int*)d_in[4];
    const int* src2 = (const int*)d_in[5];
    const int* dst2 = (const int*)d_in[6];
    const int* gid2 = (const int*)d_in[7];
    const float* W  = (const float*)d_in[8];
    const float* b  = (const float*)d_in[9];
    const float* Wc = (const float*)d_in[10];
    const float* bc = (const float*)d_in[11];

    const int NN = in_sizes[0] / FEATS;
    const int E1 = in_sizes[2], E2 = in_sizes[5];
    const int nblk = (NN + SCAN_TILE - 1) / SCAN_TILE;

    // one-time stream/event setup (host-side resources only; no device mem)
    static cudaStream_t s2 = nullptr;
    static cudaEvent_t evF = nullptr, evJ = nullptr;
    if (s2 == nullptr) {
        cudaStreamCreateWithFlags(&s2, cudaStreamNonBlocking);
        cudaEventCreateWithFlags(&evF, cudaEventDisableTiming);
        cudaEventCreateWithFlags(&evJ, cudaEventDisableTiming);
    }

    void *p_deg_out, *p_deg_in, *p_hg, *p_cnt;
    cudaGetSymbolAddress(&p_deg_out, g_deg_out);
    cudaGetSymbolAddress(&p_deg_in,  g_deg_in);
    cudaGetSymbolAddress(&p_hg,      g_hg);
    cudaGetSymbolAddress(&p_cnt,     g_cnt);

    const int SMEM = 2 * 128 * AS * (int)sizeof(__half);  // 69632
    cudaFuncSetAttribute(gemm_fp16_kernel,
                         cudaFuncAttributeMaxDynamicSharedMemorySize, SMEM);

    cudaMemsetAsync(p_hg, 0, 2 * NGRAPH * FEATS * sizeof(float));
    cudaMemsetAsync(p_cnt, 0, 2 * NGRAPH * sizeof(int));
    cudaMemsetAsync(p_deg_out, 0, 2 * N_NODES_MAX * sizeof(int));
    cudaMemsetAsync(p_deg_in,  0, 2 * N_NODES_MAX * sizeof(int));

    prep_wt_kernel<<<64, 256>>>(W);
    degree2_kernel<<<(E1 + E2 + 255) / 256, 256>>>(src1, dst1, E1, src2, dst2, E2);

    // ---- fork: CSR build on s2, GEMM on main stream (independent) ----
    cudaEventRecord(evF, 0);
    cudaStreamWaitEvent(s2, evF, 0);
    {
        dim3 grid(nblk, 2);
        reduce_kernel<<<grid, 1024, 0, s2>>>(NN);
        scan_part_kernel<<<1, 64, 0, s2>>>(nblk);
        local_scan_kernel<<<grid, 1024, 0, s2>>>(NN);
    }
    fill2_kernel<<<(E1 + E2 + 255) / 256, 256, 0, s2>>>(src1, dst1, E1, src2, dst2, E2);
    cudaEventRecord(evJ, s2);

    {
        dim3 grid((NN + 127) / 128, 2);
        gemm_fp16_kernel<<<grid, 256, SMEM>>>(feat1, feat2, NN);
    }
    cudaStreamWaitEvent(0, evJ, 0);
    // ---- join ----

    {
        long long threads = (long long)2 * NN * 16;
        int blocks = (int)((threads + 255) / 256);
        gather2_kernel<<<blocks, 256>>>(gid1, gid2, b, NN);
    }
    final_kernel<<<NGRAPH, 64>>>(Wc, bc, (float*)d_out);
}

// round 9
// speedup vs baseline: 1.1948x; 1.1948x over previous
#include <cuda_runtime.h>
#include <cuda_fp16.h>
#include <cuda_bf16.h>

#define N_NODES_MAX 100352
#define N_EDGES_MAX 1605632
#define FEATS 128
#define NGRAPH 128
#define NCLASS 64
#define SCAN_TILE 4096

// ---------------- scratch (device globals) ----------------------------------
__device__ int    g_deg_out[2][N_NODES_MAX];
__device__ int    g_deg_in[2][N_NODES_MAX];
__device__ int    g_row_ptr[2][N_NODES_MAX];
__device__ int    g_cursor[2][N_NODES_MAX];
__device__ int    g_csr_src[2][N_EDGES_MAX];
__device__ __half g_h[2][(size_t)N_NODES_MAX * FEATS];
__device__ __half g_WT[FEATS * FEATS];           // W^T in fp16: [n][k]
__device__ float  g_hg[2 * NGRAPH * FEATS];
__device__ int    g_cnt[2 * NGRAPH];
// decoupled-lookback scan state
__device__ int                g_tile_counter[2];
__device__ unsigned long long g_tile_state[2][64];   // (flag<<32)|value

// ------- degrees (both branches) + W prep + scan-state reset, one kernel -----
__global__ void degree_prep_kernel(const int* __restrict__ s1, const int* __restrict__ d1, int E1,
                                   const int* __restrict__ s2, const int* __restrict__ d2, int E2,
                                   const float* __restrict__ W, int nb_edges) {
    int blk = blockIdx.x, tid = threadIdx.x;
    if (blk < nb_edges) {
        int e = blk * 256 + tid;
        if (e < E1) {
            atomicAdd(&g_deg_out[0][s1[e]], 1);
            atomicAdd(&g_deg_in[0][d1[e]], 1);
        } else if (e < E1 + E2) {
            int i = e - E1;
            atomicAdd(&g_deg_out[1][s2[i]], 1);
            atomicAdd(&g_deg_in[1][d2[i]], 1);
        }
    } else if (blk < nb_edges + 64) {
        int t = (blk - nb_edges) * 256 + tid;     // 0..16383
        int k = t >> 7, n = t & 127;
        g_WT[n * 128 + k] = __float2half_rn(W[k * 128 + n]);
    } else {
        if (tid < 2)   g_tile_counter[tid] = 0;
        if (tid < 128) g_tile_state[tid >> 6][tid & 63] = 0ull;
    }
}

// -------- decoupled-lookback scan of deg_in -> row_ptr & cursor --------------
// grid (nblk, 2), block 1024, tile 4096 (4 per thread)
__global__ void scan_lookback_kernel(int nnodes) {
    const int br = blockIdx.y;
    __shared__ int s_tile;
    __shared__ int ws[32];
    __shared__ int s_base;

    if (threadIdx.x == 0) s_tile = atomicAdd(&g_tile_counter[br], 1);
    __syncthreads();
    const int blk = s_tile;

    int i = blk * SCAN_TILE + threadIdx.x * 4;
    int lane = threadIdx.x & 31, w = threadIdx.x >> 5;
    int4 v = make_int4(0, 0, 0, 0);
    if (i + 3 < nnodes) v = *(const int4*)&g_deg_in[br][i];
    else {
        if (i     < nnodes) v.x = g_deg_in[br][i];
        if (i + 1 < nnodes) v.y = g_deg_in[br][i + 1];
        if (i + 2 < nnodes) v.z = g_deg_in[br][i + 2];
    }
    int s0 = v.x, s1 = s0 + v.y, s2 = s1 + v.z, s3 = s2 + v.w;
    int x = s3;
#pragma unroll
    for (int o = 1; o < 32; o <<= 1) {
        int y = __shfl_up_sync(0xffffffffu, x, o);
        if (lane >= o) x += y;
    }
    if (lane == 31) ws[w] = x;
    __syncthreads();
    if (w == 0) {
        int t = ws[lane];
#pragma unroll
        for (int o = 1; o < 32; o <<= 1) {
            int y = __shfl_up_sync(0xffffffffu, t, o);
            if (lane >= o) t += y;
        }
        ws[lane] = t;
    }
    __syncthreads();
    const int total = ws[31];

    // publish + lookback (thread 0)
    if (threadIdx.x == 0) {
        volatile unsigned long long* st = g_tile_state[br];
        if (blk == 0) {
            st[0] = (2ull << 32) | (unsigned)total;
            s_base = 0;
        } else {
            st[blk] = (1ull << 32) | (unsigned)total;
            int base = 0;
            int p = blk - 1;
            while (p >= 0) {
                unsigned long long vv;
                do { vv = st[p]; } while ((vv >> 32) == 0ull);
                if ((vv >> 32) == 2ull) { base += (int)(unsigned)vv; break; }
                base += (int)(unsigned)vv;
                p--;
            }
            st[blk] = (2ull << 32) | (unsigned)(base + total);
            s_base = base;
        }
    }
    __syncthreads();

    int base = s_base + (w ? ws[w - 1] : 0) + (x - s3);
    int4 e = make_int4(base, base + s0, base + s1, base + s2);
    if (i + 3 < nnodes) {
        *(int4*)&g_row_ptr[br][i] = e;
        *(int4*)&g_cursor[br][i]  = e;
    } else {
        if (i     < nnodes) { g_row_ptr[br][i]     = e.x; g_cursor[br][i]     = e.x; }
        if (i + 1 < nnodes) { g_row_ptr[br][i + 1] = e.y; g_cursor[br][i + 1] = e.y; }
        if (i + 2 < nnodes) { g_row_ptr[br][i + 2] = e.z; g_cursor[br][i + 2] = e.z; }
    }
}

// ---------------- CSR fill, both branches ------------------------------------
__global__ void fill2_kernel(const int* __restrict__ s1, const int* __restrict__ d1, int E1,
                             const int* __restrict__ s2, const int* __restrict__ d2, int E2) {
    int e = blockIdx.x * blockDim.x + threadIdx.x;
    if (e < E1) {
        int pos = atomicAdd(&g_cursor[0][d1[e]], 1);
        g_csr_src[0][pos] = s1[e];
    } else if (e < E1 + E2) {
        int i = e - E1;
        int pos = atomicAdd(&g_cursor[1][d2[i]], 1);
        g_csr_src[1][pos] = s2[i];
    }
}

// ---------------- fp16 MMA helper --------------------------------------------
__device__ __forceinline__ void mma_f16(float4& c,
                                        unsigned a0, unsigned a1,
                                        unsigned a2, unsigned a3,
                                        unsigned b0, unsigned b1) {
    asm volatile(
        "mma.sync.aligned.m16n8k16.row.col.f32.f16.f16.f32 "
        "{%0,%1,%2,%3}, {%4,%5,%6,%7}, {%8,%9}, {%0,%1,%2,%3};\n"
        : "+f"(c.x), "+f"(c.y), "+f"(c.z), "+f"(c.w)
        : "r"(a0), "r"(a1), "r"(a2), "r"(a3), "r"(b0), "r"(b1));
}

// ---------------- GEMM (fp16 HMMA): g_h[br] = ds * (feat @ W), fp16 out ------
#define AS 136  // half stride per smem row (272B) -> conflict-free
__global__ void __launch_bounds__(256, 2)
gemm_fp16_kernel(const float* __restrict__ feat0, const float* __restrict__ feat1,
                 int nnodes) {
    extern __shared__ __half sm[];
    __half* sA  = sm;              // [128][AS]  feat tile (fp16), row-major
    __half* sBt = sm + 128 * AS;   // [128][AS]  W^T: [n][k]

    const int br   = blockIdx.y;
    const float* feat = br ? feat1 : feat0;
    const int tid  = threadIdx.x;
    const int row0 = blockIdx.x * 128;
    const float4* F4  = (const float4*)feat;
    const uint4*  WT4 = (const uint4*)g_WT;

#pragma unroll
    for (int i = 0; i < 8; i++) {
        int idx = tid + i * 256;          // 2048 uint4 total
        int r = idx >> 4, c = idx & 15;   // row, uint4-col (8 halves)
        float4 f0 = make_float4(0.f, 0.f, 0.f, 0.f), f1 = f0;
        if (row0 + r < nnodes) {
            f0 = F4[(size_t)(row0 + r) * 32 + 2 * c];
            f1 = F4[(size_t)(row0 + r) * 32 + 2 * c + 1];
        }
        union { __half2 h[4]; uint4 u; } p;
        p.h[0] = __floats2half2_rn(f0.x, f0.y);
        p.h[1] = __floats2half2_rn(f0.z, f0.w);
        p.h[2] = __floats2half2_rn(f1.x, f1.y);
        p.h[3] = __floats2half2_rn(f1.z, f1.w);
        *(uint4*)&sA[r * AS + c * 8] = p.u;
        *(uint4*)&sBt[r * AS + c * 8] = WT4[idx];
    }
    __syncthreads();

    const int w = tid >> 5, lane = tid & 31;
    const int gid8 = lane >> 2, tig = lane & 3;
    const int r0 = w * 16;

    float4 c[16];
#pragma unroll
    for (int j = 0; j < 16; j++) c[j] = make_float4(0.f, 0.f, 0.f, 0.f);

#pragma unroll
    for (int kk = 0; kk < 8; kk++) {
        int k0 = kk * 16;
        unsigned a0 = *(const unsigned*)&sA[(r0 + gid8) * AS + k0 + 2 * tig];
        unsigned a1 = *(const unsigned*)&sA[(r0 + gid8 + 8) * AS + k0 + 2 * tig];
        unsigned a2 = *(const unsigned*)&sA[(r0 + gid8) * AS + k0 + 8 + 2 * tig];
        unsigned a3 = *(const unsigned*)&sA[(r0 + gid8 + 8) * AS + k0 + 8 + 2 * tig];
#pragma unroll
        for (int j = 0; j < 16; j++) {
            unsigned b0 = *(const unsigned*)&sBt[(j * 8 + gid8) * AS + k0 + 2 * tig];
            unsigned b1 = *(const unsigned*)&sBt[(j * 8 + gid8) * AS + k0 + 8 + 2 * tig];
            mma_f16(c[j], a0, a1, a2, a3, b0, b1);
        }
    }

    int ra = row0 + r0 + gid8;
    int rb = ra + 8;
    bool va = ra < nnodes, vb = rb < nnodes;
    float dsa = 0.f, dsb = 0.f;
    if (va) { int d = g_deg_out[br][ra]; dsa = rsqrtf((float)(d > 1 ? d : 1)); }
    if (vb) { int d = g_deg_out[br][rb]; dsb = rsqrtf((float)(d > 1 ? d : 1)); }
    unsigned* H = (unsigned*)g_h[br];
#pragma unroll
    for (int j = 0; j < 16; j++) {
        int colw = j * 4 + tig;  // half2 index within row (64 per row)
        if (va) {
            __half2 o = __floats2half2_rn(c[j].x * dsa, c[j].y * dsa);
            H[(size_t)ra * 64 + colw] = *(unsigned*)&o;
        }
        if (vb) {
            __half2 o = __floats2half2_rn(c[j].z * dsb, c[j].w * dsb);
            H[(size_t)rb * 64 + colw] = *(unsigned*)&o;
        }
    }
}

// ---------------- gather-aggregate + fused epilogue (warp per node) ----------
__global__ void gather2_kernel(const int* __restrict__ gid0,
                               const int* __restrict__ gid1,
                               const float* __restrict__ bvec, int nnodes) {
    int t = blockIdx.x * blockDim.x + threadIdx.x;
    int n2 = t >> 5;
    if (n2 >= 2 * nnodes) return;
    int br = (n2 >= nnodes) ? 1 : 0;
    int n = n2 - br * nnodes;
    int lane = t & 31;

    int beg = g_row_ptr[br][n];
    int dg  = g_deg_in[br][n];
    int end = beg + dg;
    const uint2* H2 = (const uint2*)g_h[br];   // 8B per lane = 4 halves
    const int* csr = g_csr_src[br];

    float4 acc = make_float4(0.f, 0.f, 0.f, 0.f);
    int e = beg;
    for (; e + 4 <= end; e += 4) {
        int s0 = __ldg(csr + e);
        int s1 = __ldg(csr + e + 1);
        int s2 = __ldg(csr + e + 2);
        int s3 = __ldg(csr + e + 3);
        uint2 u0 = H2[(size_t)s0 * 32 + lane];
        uint2 u1 = H2[(size_t)s1 * 32 + lane];
        uint2 u2 = H2[(size_t)s2 * 32 + lane];
        uint2 u3 = H2[(size_t)s3 * 32 + lane];
        float2 f;
        f = __half22float2(*(__half2*)&u0.x); acc.x += f.x; acc.y += f.y;
        f = __half22float2(*(__half2*)&u0.y); acc.z += f.x; acc.w += f.y;
        f = __half22float2(*(__half2*)&u1.x); acc.x += f.x; acc.y += f.y;
        f = __half22float2(*(__half2*)&u1.y); acc.z += f.x; acc.w += f.y;
        f = __half22float2(*(__half2*)&u2.x); acc.x += f.x; acc.y += f.y;
        f = __half22float2(*(__half2*)&u2.y); acc.z += f.x; acc.w += f.y;
        f = __half22float2(*(__half2*)&u3.x); acc.x += f.x; acc.y += f.y;
        f = __half22float2(*(__half2*)&u3.y); acc.z += f.x; acc.w += f.y;
    }
    for (; e < end; e++) {
        int s = __ldg(csr + e);
        uint2 u = H2[(size_t)s * 32 + lane];
        float2 f;
        f = __half22float2(*(__half2*)&u.x); acc.x += f.x; acc.y += f.y;
        f = __half22float2(*(__half2*)&u.y); acc.z += f.x; acc.w += f.y;
    }

    float din = rsqrtf((float)(dg > 1 ? dg : 1));
    float4 bb = __ldg((const float4*)bvec + lane);
    float4 v = make_float4(acc.x * din + bb.x, acc.y * din + bb.y,
                           acc.z * din + bb.z, acc.w * din + bb.w);
    float ss = v.x * v.x + v.y * v.y + v.z * v.z + v.w * v.w;
#pragma unroll
    for (int o = 16; o; o >>= 1) ss += __shfl_xor_sync(0xffffffffu, ss, o);
    float inv = 1.f / fmaxf(sqrtf(ss), 1e-12f);

    v.x = 1.f / (1.f + __expf(-v.x * inv));
    v.y = 1.f / (1.f + __expf(-v.y * inv));
    v.z = 1.f / (1.f + __expf(-v.z * inv));
    v.w = 1.f / (1.f + __expf(-v.w * inv));

    const int* gid = br ? gid1 : gid0;
    int g = __ldg(gid + n);
    atomicAdd((float4*)g_hg + (size_t)(br * NGRAPH + g) * 32 + lane, v);
    if (lane == 0) atomicAdd(&g_cnt[br * NGRAPH + g], 1);
}

// ---------------- classifier + pairwise distance (block per graph) -----------
__global__ void final_kernel(const float* __restrict__ Wc,
                             const float* __restrict__ bc,
                             float* __restrict__ out) {
    int g = blockIdx.x, tid = threadIdx.x;  // 64 threads
    __shared__ float s1[128], s2[128];
    __shared__ float part[2];

    float c1 = fmaxf((float)g_cnt[g], 1.f);
    float c2 = fmaxf((float)g_cnt[NGRAPH + g], 1.f);
    for (int i = tid; i < 128; i += 64) {
        s1[i] = g_hg[g * 128 + i] / c1;
        s2[i] = g_hg[NGRAPH * 128 + g * 128 + i] / c2;
    }
    __syncthreads();

    float l1 = bc[tid], l2 = l1;
#pragma unroll 4
    for (int k = 0; k < 128; k++) {
        float w = Wc[k * NCLASS + tid];
        l1 += s1[k] * w;
        l2 += s2[k] * w;
    }
    float dd = l1 - l2 + 1e-6f;
    float sq = dd * dd;
#pragma unroll
    for (int o = 16; o; o >>= 1) sq += __shfl_xor_sync(0xffffffffu, sq, o);
    if ((tid & 31) == 0) part[tid >> 5] = sq;
    __syncthreads();
    if (tid == 0) out[g] = sqrtf(part[0] + part[1]);
}

// ---------------- launch ------------------------------------------------------
extern "C" void kernel_launch(void* const* d_in, const int* in_sizes, int n_in,
                              void* d_out, int out_size) {
    const float* feat1 = (const float*)d_in[0];
    const float* feat2 = (const float*)d_in[1];
    const int* src1 = (const int*)d_in[2];
    const int* dst1 = (const int*)d_in[3];
    const int* gid1 = (const int*)d_in[4];
    const int* src2 = (const int*)d_in[5];
    const int* dst2 = (const int*)d_in[6];
    const int* gid2 = (const int*)d_in[7];
    const float* W  = (const float*)d_in[8];
    const float* b  = (const float*)d_in[9];
    const float* Wc = (const float*)d_in[10];
    const float* bc = (const float*)d_in[11];

    const int NN = in_sizes[0] / FEATS;
    const int E1 = in_sizes[2], E2 = in_sizes[5];
    const int nblk = (NN + SCAN_TILE - 1) / SCAN_TILE;

    void *p_deg_out, *p_deg_in, *p_hg, *p_cnt;
    cudaGetSymbolAddress(&p_deg_out, g_deg_out);
    cudaGetSymbolAddress(&p_deg_in,  g_deg_in);
    cudaGetSymbolAddress(&p_hg,      g_hg);
    cudaGetSymbolAddress(&p_cnt,     g_cnt);

    const int SMEM = 2 * 128 * AS * (int)sizeof(__half);  // 69632
    cudaFuncSetAttribute(gemm_fp16_kernel,
                         cudaFuncAttributeMaxDynamicSharedMemorySize, SMEM);

    cudaMemsetAsync(p_hg, 0, 2 * NGRAPH * FEATS * sizeof(float));
    cudaMemsetAsync(p_cnt, 0, 2 * NGRAPH * sizeof(int));
    cudaMemsetAsync(p_deg_out, 0, 2 * N_NODES_MAX * sizeof(int));
    cudaMemsetAsync(p_deg_in,  0, 2 * N_NODES_MAX * sizeof(int));

    const int nb_edges = (E1 + E2 + 255) / 256;
    degree_prep_kernel<<<nb_edges + 65, 256>>>(src1, dst1, E1, src2, dst2, E2, W, nb_edges);

    {
        dim3 grid(nblk, 2);
        scan_lookback_kernel<<<grid, 1024>>>(NN);
    }
    fill2_kernel<<<(E1 + E2 + 255) / 256, 256>>>(src1, dst1, E1, src2, dst2, E2);

    {
        dim3 grid((NN + 127) / 128, 2);
        gemm_fp16_kernel<<<grid, 256, SMEM>>>(feat1, feat2, NN);
    }
    {
        long long threads = (long long)2 * NN * 32;
        int blocks = (int)((threads + 255) / 256);
        gather2_kernel<<<blocks, 256>>>(gid1, gid2, b, NN);
    }
    final_kernel<<<NGRAPH, 64>>>(Wc, bc, (float*)d_out);
}

// round 10
// speedup vs baseline: 1.2105x; 1.0131x over previous
#include <cuda_runtime.h>
#include <cuda_fp16.h>
#include <cuda_bf16.h>

#define N_NODES_MAX 100352
#define N_EDGES_MAX 1605632
#define FEATS 128
#define NGRAPH 128
#define NCLASS 64
#define SCAN_TILE 4096

// ---------------- scratch (device globals) ----------------------------------
__device__ int    g_deg_out[2][N_NODES_MAX];
__device__ int    g_deg_in[2][N_NODES_MAX];
__device__ int    g_row_ptr[2][N_NODES_MAX];
__device__ int    g_cursor[2][N_NODES_MAX];
__device__ int    g_csr_src[2][N_EDGES_MAX];
__device__ __half g_h[2][(size_t)N_NODES_MAX * FEATS];
__device__ __half g_WT[FEATS * FEATS];           // W^T in fp16: [n][k]
__device__ float  g_hg[2 * NGRAPH * FEATS];
__device__ int    g_cnt[2 * NGRAPH];
// decoupled-lookback scan state
__device__ int                g_tile_counter[2];
__device__ unsigned long long g_tile_state[2][64];   // (flag<<32)|value

// ------- degrees (both branches) + W prep + scan-state reset, one kernel -----
__global__ void degree_prep_kernel(const int* __restrict__ s1, const int* __restrict__ d1, int E1,
                                   const int* __restrict__ s2, const int* __restrict__ d2, int E2,
                                   const float* __restrict__ W, int nb_edges) {
    int blk = blockIdx.x, tid = threadIdx.x;
    if (blk < nb_edges) {
        int e = blk * 256 + tid;
        if (e < E1) {
            atomicAdd(&g_deg_out[0][s1[e]], 1);
            atomicAdd(&g_deg_in[0][d1[e]], 1);
        } else if (e < E1 + E2) {
            int i = e - E1;
            atomicAdd(&g_deg_out[1][s2[i]], 1);
            atomicAdd(&g_deg_in[1][d2[i]], 1);
        }
    } else if (blk < nb_edges + 64) {
        int t = (blk - nb_edges) * 256 + tid;     // 0..16383
        int k = t >> 7, n = t & 127;
        g_WT[n * 128 + k] = __float2half_rn(W[k * 128 + n]);
    } else {
        if (tid < 2)   g_tile_counter[tid] = 0;
        if (tid < 128) g_tile_state[tid >> 6][tid & 63] = 0ull;
    }
}

// -------- decoupled-lookback scan of deg_in -> row_ptr & cursor --------------
__global__ void scan_lookback_kernel(int nnodes) {
    const int br = blockIdx.y;
    __shared__ int s_tile;
    __shared__ int ws[32];
    __shared__ int s_base;

    if (threadIdx.x == 0) s_tile = atomicAdd(&g_tile_counter[br], 1);
    __syncthreads();
    const int blk = s_tile;

    int i = blk * SCAN_TILE + threadIdx.x * 4;
    int lane = threadIdx.x & 31, w = threadIdx.x >> 5;
    int4 v = make_int4(0, 0, 0, 0);
    if (i + 3 < nnodes) v = *(const int4*)&g_deg_in[br][i];
    else {
        if (i     < nnodes) v.x = g_deg_in[br][i];
        if (i + 1 < nnodes) v.y = g_deg_in[br][i + 1];
        if (i + 2 < nnodes) v.z = g_deg_in[br][i + 2];
    }
    int s0 = v.x, s1 = s0 + v.y, s2 = s1 + v.z, s3 = s2 + v.w;
    int x = s3;
#pragma unroll
    for (int o = 1; o < 32; o <<= 1) {
        int y = __shfl_up_sync(0xffffffffu, x, o);
        if (lane >= o) x += y;
    }
    if (lane == 31) ws[w] = x;
    __syncthreads();
    if (w == 0) {
        int t = ws[lane];
#pragma unroll
        for (int o = 1; o < 32; o <<= 1) {
            int y = __shfl_up_sync(0xffffffffu, t, o);
            if (lane >= o) t += y;
        }
        ws[lane] = t;
    }
    __syncthreads();
    const int total = ws[31];

    if (threadIdx.x == 0) {
        volatile unsigned long long* st = g_tile_state[br];
        if (blk == 0) {
            st[0] = (2ull << 32) | (unsigned)total;
            s_base = 0;
        } else {
            st[blk] = (1ull << 32) | (unsigned)total;
            int base = 0;
            int p = blk - 1;
            while (p >= 0) {
                unsigned long long vv;
                do { vv = st[p]; } while ((vv >> 32) == 0ull);
                if ((vv >> 32) == 2ull) { base += (int)(unsigned)vv; break; }
                base += (int)(unsigned)vv;
                p--;
            }
            st[blk] = (2ull << 32) | (unsigned)(base + total);
            s_base = base;
        }
    }
    __syncthreads();

    int base = s_base + (w ? ws[w - 1] : 0) + (x - s3);
    int4 e = make_int4(base, base + s0, base + s1, base + s2);
    if (i + 3 < nnodes) {
        *(int4*)&g_row_ptr[br][i] = e;
        *(int4*)&g_cursor[br][i]  = e;
    } else {
        if (i     < nnodes) { g_row_ptr[br][i]     = e.x; g_cursor[br][i]     = e.x; }
        if (i + 1 < nnodes) { g_row_ptr[br][i + 1] = e.y; g_cursor[br][i + 1] = e.y; }
        if (i + 2 < nnodes) { g_row_ptr[br][i + 2] = e.z; g_cursor[br][i + 2] = e.z; }
    }
}

// ---------------- CSR fill, both branches ------------------------------------
__global__ void fill2_kernel(const int* __restrict__ s1, const int* __restrict__ d1, int E1,
                             const int* __restrict__ s2, const int* __restrict__ d2, int E2) {
    int e = blockIdx.x * blockDim.x + threadIdx.x;
    if (e < E1) {
        int pos = atomicAdd(&g_cursor[0][d1[e]], 1);
        g_csr_src[0][pos] = s1[e];
    } else if (e < E1 + E2) {
        int i = e - E1;
        int pos = atomicAdd(&g_cursor[1][d2[i]], 1);
        g_csr_src[1][pos] = s2[i];
    }
}

// ---------------- fp16 MMA / ldmatrix helpers --------------------------------
__device__ __forceinline__ void mma_f16(float4& c,
                                        unsigned a0, unsigned a1,
                                        unsigned a2, unsigned a3,
                                        unsigned b0, unsigned b1) {
    asm volatile(
        "mma.sync.aligned.m16n8k16.row.col.f32.f16.f16.f32 "
        "{%0,%1,%2,%3}, {%4,%5,%6,%7}, {%8,%9}, {%0,%1,%2,%3};\n"
        : "+f"(c.x), "+f"(c.y), "+f"(c.z), "+f"(c.w)
        : "r"(a0), "r"(a1), "r"(a2), "r"(a3), "r"(b0), "r"(b1));
}

__device__ __forceinline__ void ldsm_x4(unsigned& r0, unsigned& r1,
                                        unsigned& r2, unsigned& r3, unsigned addr) {
    asm volatile("ldmatrix.sync.aligned.m8n8.x4.shared.b16 {%0,%1,%2,%3}, [%4];"
                 : "=r"(r0), "=r"(r1), "=r"(r2), "=r"(r3) : "r"(addr));
}
__device__ __forceinline__ void ldsm_x2(unsigned& r0, unsigned& r1, unsigned addr) {
    asm volatile("ldmatrix.sync.aligned.m8n8.x2.shared.b16 {%0,%1}, [%2];"
                 : "=r"(r0), "=r"(r1) : "r"(addr));
}

// ---------------- GEMM (fp16 HMMA + ldmatrix): g_h[br] = ds * (feat @ W) -----
// block 256 (8 warps as 4x2), tile 128x128, K=128; warp tile m32 x n64
#define AS 136  // half stride per smem row (272B, 16B-multiple -> ldmatrix ok)
__global__ void __launch_bounds__(256, 2)
gemm_fp16_kernel(const float* __restrict__ feat0, const float* __restrict__ feat1,
                 int nnodes) {
    extern __shared__ __half sm[];
    __half* sA  = sm;              // [128][AS]  feat tile (fp16), row-major
    __half* sBt = sm + 128 * AS;   // [128][AS]  W^T: [n][k]

    const int br   = blockIdx.y;
    const float* feat = br ? feat1 : feat0;
    const int tid  = threadIdx.x;
    const int row0 = blockIdx.x * 128;
    const float4* F4  = (const float4*)feat;
    const uint4*  WT4 = (const uint4*)g_WT;

#pragma unroll
    for (int i = 0; i < 8; i++) {
        int idx = tid + i * 256;          // 2048 uint4 total
        int r = idx >> 4, c = idx & 15;   // row, uint4-col (8 halves)
        float4 f0 = make_float4(0.f, 0.f, 0.f, 0.f), f1 = f0;
        if (row0 + r < nnodes) {
            f0 = F4[(size_t)(row0 + r) * 32 + 2 * c];
            f1 = F4[(size_t)(row0 + r) * 32 + 2 * c + 1];
        }
        union { __half2 h[4]; uint4 u; } p;
        p.h[0] = __floats2half2_rn(f0.x, f0.y);
        p.h[1] = __floats2half2_rn(f0.z, f0.w);
        p.h[2] = __floats2half2_rn(f1.x, f1.y);
        p.h[3] = __floats2half2_rn(f1.z, f1.w);
        *(uint4*)&sA[r * AS + c * 8] = p.u;
        *(uint4*)&sBt[r * AS + c * 8] = WT4[idx];
    }
    __syncthreads();

    const int w = tid >> 5, lane = tid & 31;
    const int wm = w & 3, wn = w >> 1 & 2 ? 0 : 0;  // placeholder (computed below)
    (void)wn;
    const int warp_n = w >> 2;             // 0..1
    const int r0 = wm * 32;                // warp row base within tile
    const int n0 = warp_n * 64;            // warp col base
    const int gid8 = lane >> 2, tig = lane & 3;

    // ldmatrix source addresses (shared-state-space)
    unsigned aAddr0 = (unsigned)__cvta_generic_to_shared(
        &sA[(r0 + (lane & 15)) * AS + (lane >> 4) * 8]);
    unsigned aAddr1 = (unsigned)__cvta_generic_to_shared(
        &sA[(r0 + 16 + (lane & 15)) * AS + (lane >> 4) * 8]);
    int bl = lane & 15;
    unsigned bAddr = (unsigned)__cvta_generic_to_shared(
        &sBt[(n0 + (bl & 7)) * AS + (bl >> 3) * 8]);

    float4 c[2][8];
#pragma unroll
    for (int m = 0; m < 2; m++)
#pragma unroll
        for (int j = 0; j < 8; j++) c[m][j] = make_float4(0.f, 0.f, 0.f, 0.f);

#pragma unroll
    for (int kk = 0; kk < 8; kk++) {
        unsigned koff = kk * 32;           // 16 halves = 32 bytes
        unsigned a[2][4];
        ldsm_x4(a[0][0], a[0][1], a[0][2], a[0][3], aAddr0 + koff);
        ldsm_x4(a[1][0], a[1][1], a[1][2], a[1][3], aAddr1 + koff);
        unsigned b[8][2];
#pragma unroll
        for (int j = 0; j < 8; j++)
            ldsm_x2(b[j][0], b[j][1], bAddr + j * (8 * AS * 2) + koff);
#pragma unroll
        for (int m = 0; m < 2; m++)
#pragma unroll
            for (int j = 0; j < 8; j++)
                mma_f16(c[m][j], a[m][0], a[m][1], a[m][2], a[m][3],
                        b[j][0], b[j][1]);
    }

    unsigned* H = (unsigned*)g_h[br];
#pragma unroll
    for (int m = 0; m < 2; m++) {
        int ra = row0 + r0 + m * 16 + gid8;
        int rb = ra + 8;
        bool va = ra < nnodes, vb = rb < nnodes;
        float dsa = 0.f, dsb = 0.f;
        if (va) { int d = g_deg_out[br][ra]; dsa = rsqrtf((float)(d > 1 ? d : 1)); }
        if (vb) { int d = g_deg_out[br][rb]; dsb = rsqrtf((float)(d > 1 ? d : 1)); }
#pragma unroll
        for (int j = 0; j < 8; j++) {
            int colw = (n0 + j * 8 + 2 * tig) >> 1;  // half2 index (64 per row)
            if (va) {
                __half2 o = __floats2half2_rn(c[m][j].x * dsa, c[m][j].y * dsa);
                H[(size_t)ra * 64 + colw] = *(unsigned*)&o;
            }
            if (vb) {
                __half2 o = __floats2half2_rn(c[m][j].z * dsb, c[m][j].w * dsb);
                H[(size_t)rb * 64 + colw] = *(unsigned*)&o;
            }
        }
    }
}

// ---------------- gather-aggregate + fused epilogue (warp per node) ----------
__global__ void gather2_kernel(const int* __restrict__ gid0,
                               const int* __restrict__ gid1,
                               const float* __restrict__ bvec, int nnodes) {
    int t = blockIdx.x * blockDim.x + threadIdx.x;
    int n2 = t >> 5;
    if (n2 >= 2 * nnodes) return;
    int br = (n2 >= nnodes) ? 1 : 0;
    int n = n2 - br * nnodes;
    int lane = t & 31;

    int beg = __ldg(&g_row_ptr[br][n]);
    int dg  = __ldg(&g_deg_in[br][n]);
    int end = beg + dg;
    const uint2* H2 = (const uint2*)g_h[br];   // 8B per lane = 4 halves
    const int* csr = g_csr_src[br];

    float4 acc = make_float4(0.f, 0.f, 0.f, 0.f);

#define ACCU(u) { float2 f_; \
    f_ = __half22float2(*(__half2*)&(u).x); acc.x += f_.x; acc.y += f_.y; \
    f_ = __half22float2(*(__half2*)&(u).y); acc.z += f_.x; acc.w += f_.y; }

    int e = beg;
    for (; e + 8 <= end; e += 8) {
        int s0 = __ldg(csr + e);
        int s1 = __ldg(csr + e + 1);
        int s2 = __ldg(csr + e + 2);
        int s3 = __ldg(csr + e + 3);
        int s4 = __ldg(csr + e + 4);
        int s5 = __ldg(csr + e + 5);
        int s6 = __ldg(csr + e + 6);
        int s7 = __ldg(csr + e + 7);
        uint2 u0 = H2[(size_t)s0 * 32 + lane];
        uint2 u1 = H2[(size_t)s1 * 32 + lane];
        uint2 u2 = H2[(size_t)s2 * 32 + lane];
        uint2 u3 = H2[(size_t)s3 * 32 + lane];
        uint2 u4 = H2[(size_t)s4 * 32 + lane];
        uint2 u5 = H2[(size_t)s5 * 32 + lane];
        uint2 u6 = H2[(size_t)s6 * 32 + lane];
        uint2 u7 = H2[(size_t)s7 * 32 + lane];
        ACCU(u0); ACCU(u1); ACCU(u2); ACCU(u3);
        ACCU(u4); ACCU(u5); ACCU(u6); ACCU(u7);
    }
    for (; e + 2 <= end; e += 2) {
        int s0 = __ldg(csr + e);
        int s1 = __ldg(csr + e + 1);
        uint2 u0 = H2[(size_t)s0 * 32 + lane];
        uint2 u1 = H2[(size_t)s1 * 32 + lane];
        ACCU(u0); ACCU(u1);
    }
    if (e < end) {
        int s = __ldg(csr + e);
        uint2 u = H2[(size_t)s * 32 + lane];
        ACCU(u);
    }
#undef ACCU

    float din = rsqrtf((float)(dg > 1 ? dg : 1));
    float4 bb = __ldg((const float4*)bvec + lane);
    float4 v = make_float4(acc.x * din + bb.x, acc.y * din + bb.y,
                           acc.z * din + bb.z, acc.w * din + bb.w);
    float ss = v.x * v.x + v.y * v.y + v.z * v.z + v.w * v.w;
#pragma unroll
    for (int o = 16; o; o >>= 1) ss += __shfl_xor_sync(0xffffffffu, ss, o);
    float inv = 1.f / fmaxf(sqrtf(ss), 1e-12f);

    v.x = 1.f / (1.f + __expf(-v.x * inv));
    v.y = 1.f / (1.f + __expf(-v.y * inv));
    v.z = 1.f / (1.f + __expf(-v.z * inv));
    v.w = 1.f / (1.f + __expf(-v.w * inv));

    const int* gid = br ? gid1 : gid0;
    int g = __ldg(gid + n);
    atomicAdd((float4*)g_hg + (size_t)(br * NGRAPH + g) * 32 + lane, v);
    if (lane == 0) atomicAdd(&g_cnt[br * NGRAPH + g], 1);
}

// ---------------- classifier + pairwise distance (block per graph) -----------
__global__ void final_kernel(const float* __restrict__ Wc,
                             const float* __restrict__ bc,
                             float* __restrict__ out) {
    int g = blockIdx.x, tid = threadIdx.x;  // 64 threads
    __shared__ float s1[128], s2[128];
    __shared__ float part[2];

    float c1 = fmaxf((float)g_cnt[g], 1.f);
    float c2 = fmaxf((float)g_cnt[NGRAPH + g], 1.f);
    for (int i = tid; i < 128; i += 64) {
        s1[i] = g_hg[g * 128 + i] / c1;
        s2[i] = g_hg[NGRAPH * 128 + g * 128 + i] / c2;
    }
    __syncthreads();

    float l1 = bc[tid], l2 = l1;
#pragma unroll 4
    for (int k = 0; k < 128; k++) {
        float w = Wc[k * NCLASS + tid];
        l1 += s1[k] * w;
        l2 += s2[k] * w;
    }
    float dd = l1 - l2 + 1e-6f;
    float sq = dd * dd;
#pragma unroll
    for (int o = 16; o; o >>= 1) sq += __shfl_xor_sync(0xffffffffu, sq, o);
    if ((tid & 31) == 0) part[tid >> 5] = sq;
    __syncthreads();
    if (tid == 0) out[g] = sqrtf(part[0] + part[1]);
}

// ---------------- launch ------------------------------------------------------
extern "C" void kernel_launch(void* const* d_in, const int* in_sizes, int n_in,
                              void* d_out, int out_size) {
    const float* feat1 = (const float*)d_in[0];
    const float* feat2 = (const float*)d_in[1];
    const int* src1 = (const int*)d_in[2];
    const int* dst1 = (const int*)d_in[3];
    const int* gid1 = (const int*)d_in[4];
    const int* src2 = (const int*)d_in[5];
    const int* dst2 = (const int*)d_in[6];
    const int* gid2 = (const int*)d_in[7];
    const float* W  = (const float*)d_in[8];
    const float* b  = (const float*)d_in[9];
    const float* Wc = (const float*)d_in[10];
    const float* bc = (const float*)d_in[11];

    const int NN = in_sizes[0] / FEATS;
    const int E1 = in_sizes[2], E2 = in_sizes[5];
    const int nblk = (NN + SCAN_TILE - 1) / SCAN_TILE;

    void *p_deg_out, *p_deg_in, *p_hg, *p_cnt;
    cudaGetSymbolAddress(&p_deg_out, g_deg_out);
    cudaGetSymbolAddress(&p_deg_in,  g_deg_in);
    cudaGetSymbolAddress(&p_hg,      g_hg);
    cudaGetSymbolAddress(&p_cnt,     g_cnt);

    const int SMEM = 2 * 128 * AS * (int)sizeof(__half);  // 69632
    cudaFuncSetAttribute(gemm_fp16_kernel,
                         cudaFuncAttributeMaxDynamicSharedMemorySize, SMEM);

    cudaMemsetAsync(p_hg, 0, 2 * NGRAPH * FEATS * sizeof(float));
    cudaMemsetAsync(p_cnt, 0, 2 * NGRAPH * sizeof(int));
    cudaMemsetAsync(p_deg_out, 0, 2 * N_NODES_MAX * sizeof(int));
    cudaMemsetAsync(p_deg_in,  0, 2 * N_NODES_MAX * sizeof(int));

    const int nb_edges = (E1 + E2 + 255) / 256;
    degree_prep_kernel<<<nb_edges + 65, 256>>>(src1, dst1, E1, src2, dst2, E2, W, nb_edges);

    {
        dim3 grid(nblk, 2);
        scan_lookback_kernel<<<grid, 1024>>>(NN);
    }
    fill2_kernel<<<(E1 + E2 + 255) / 256, 256>>>(src1, dst1, E1, src2, dst2, E2);

    {
        dim3 grid((NN + 127) / 128, 2);
        gemm_fp16_kernel<<<grid, 256, SMEM>>>(feat1, feat2, NN);
    }
    {
        long long threads = (long long)2 * NN * 32;
        int blocks = (int)((threads + 255) / 256);
        gather2_kernel<<<blocks, 256>>>(gid1, gid2, b, NN);
    }
    final_kernel<<<NGRAPH, 64>>>(Wc, bc, (float*)d_out);
}